// round 2
// baseline (speedup 1.0000x reference)
#include <cuda_runtime.h>
#include <cuda_bf16.h>

// out[k][d] = mult_k * sum_i W_k[eb_input[i]][d]   (offsets are mathematically dead:
// every index position belongs to some bag, and all bags are summed at the end).
// Strategy: u16-packed histogram of indices -> streaming weighted reduction over
// the three tables. Histogram is REDG-lane bound (~1 atomic/index, hard floor);
// sweep is DRAM-bound (~80MB).

#define MAX_EMB 2000000
#define CNT_WORDS ((MAX_EMB + 1) / 2)

// 4MB packed count scratch: word w holds u16 counts for rows 2w (low) and 2w+1 (high).
// Zero-initialized at load; sweep re-zeroes after reading, so every graph replay
// sees a clean state.
__device__ unsigned int g_cnt[CNT_WORDS];
// 9 double accumulators padded to 512B stride (distinct L2 slices).
__device__ double g_acc[9 * 64];

// ---------------------------------------------------------------------------
// Kernel 1: histogram. One int4 (4 indices) per thread, 4 packed REDs.
// ---------------------------------------------------------------------------
__global__ void k_hist(const int* __restrict__ idx, int n_idx) {
    int t = blockIdx.x * blockDim.x + threadIdx.x;
    int n4 = n_idx >> 2;
    if (t < n4) {
        int4 a = __ldcs((const int4*)idx + t);   // streaming: don't pollute L2
        atomicAdd(&g_cnt[a.x >> 1], 1u << ((a.x & 1) << 4));
        atomicAdd(&g_cnt[a.y >> 1], 1u << ((a.y & 1) << 4));
        atomicAdd(&g_cnt[a.z >> 1], 1u << ((a.z & 1) << 4));
        atomicAdd(&g_cnt[a.w >> 1], 1u << ((a.w & 1) << 4));
    }
    // scalar tail (n_idx not a multiple of 4)
    if (blockIdx.x == 0) {
        int rem = n_idx & 3;
        if ((int)threadIdx.x < rem) {
            int r = idx[(n4 << 2) + threadIdx.x];
            atomicAdd(&g_cnt[r >> 1], 1u << ((r & 1) << 4));
        }
    }
}

// ---------------------------------------------------------------------------
// Kernel 2: streaming sweep. Each thread handles 4 rows (3 float4 per table),
// reads 4 packed counts as one u64, zeroes them, accumulates c*W.
// ---------------------------------------------------------------------------
__global__ void k_sweep(const float* __restrict__ W0,
                        const float* __restrict__ W1,
                        const float* __restrict__ W2,
                        int num_emb) {
    int t = blockIdx.x * blockDim.x + threadIdx.x;
    int r0 = t * 4;

    float acc[9];
#pragma unroll
    for (int k = 0; k < 9; k++) acc[k] = 0.0f;

    if (r0 + 4 <= num_emb) {
        unsigned long long* cw = (unsigned long long*)&g_cnt[r0 >> 1];
        unsigned long long c = *cw;
        *cw = 0ULL;                                   // re-init for next replay
        float c0 = (float)( c        & 0xFFFFu);
        float c1 = (float)((c >> 16) & 0xFFFFu);
        float c2 = (float)((c >> 32) & 0xFFFFu);
        float c3 = (float)((c >> 48) & 0xFFFFu);

        const float* Ws[3] = {W0, W1, W2};
#pragma unroll
        for (int k = 0; k < 3; k++) {
            const float4* Wv = (const float4*)Ws[k] + 3 * t;   // 12 floats = 4 rows
            float4 a = __ldcs(Wv + 0);
            float4 b = __ldcs(Wv + 1);
            float4 d = __ldcs(Wv + 2);
            // rows: r0: a.x a.y a.z | r0+1: a.w b.x b.y | r0+2: b.z b.w d.x | r0+3: d.y d.z d.w
            acc[3 * k + 0] += c0 * a.x + c1 * a.w + c2 * b.z + c3 * d.y;
            acc[3 * k + 1] += c0 * a.y + c1 * b.x + c2 * b.w + c3 * d.z;
            acc[3 * k + 2] += c0 * a.z + c1 * b.y + c2 * d.x + c3 * d.w;
        }
    } else if (r0 < num_emb) {
        for (int r = r0; r < num_emb; r++) {
            unsigned int w = g_cnt[r >> 1];
            float c = (float)((w >> ((r & 1) << 4)) & 0xFFFFu);
            // clear this row's half-word (safe: one thread owns the tail rows' words
            // only if num_emb tail rows share words within this thread's range; rows
            // beyond num_emb are never written, their halves stay 0)
            if ((r & 1) || r + 1 >= num_emb) g_cnt[r >> 1] = 0u;
            const float* Ws[3] = {W0, W1, W2};
#pragma unroll
            for (int k = 0; k < 3; k++) {
                acc[3 * k + 0] += c * Ws[k][3 * r + 0];
                acc[3 * k + 1] += c * Ws[k][3 * r + 1];
                acc[3 * k + 2] += c * Ws[k][3 * r + 2];
            }
        }
    }

    // warp reduction
    unsigned lane = threadIdx.x & 31u;
    unsigned warp = threadIdx.x >> 5;
#pragma unroll
    for (int k = 0; k < 9; k++) {
#pragma unroll
        for (int o = 16; o > 0; o >>= 1)
            acc[k] += __shfl_down_sync(0xffffffffu, acc[k], o);
    }

    __shared__ float s_red[8][9];
    if (lane == 0) {
#pragma unroll
        for (int k = 0; k < 9; k++) s_red[warp][k] = acc[k];
    }
    __syncthreads();

    if (threadIdx.x < 9) {
        double s = 0.0;
#pragma unroll
        for (int w = 0; w < 8; w++) s += (double)s_red[w][threadIdx.x];
        atomicAdd(&g_acc[threadIdx.x * 64], s);
    }
}

// ---------------------------------------------------------------------------
// Kernel 3: scale, write output, re-zero accumulators for next replay.
// ---------------------------------------------------------------------------
__global__ void k_final(float* __restrict__ out) {
    int i = threadIdx.x;
    if (i < 9) {
        const float mult[3] = {5.0f, 10.0f, 6.0f};
        double v = g_acc[i * 64];
        g_acc[i * 64] = 0.0;
        out[i] = (float)((double)mult[i / 3] * v);
    }
}

// ---------------------------------------------------------------------------
extern "C" void kernel_launch(void* const* d_in, const int* in_sizes, int n_in,
                              void* d_out, int out_size) {
    const int*   idx = (const int*)d_in[0];
    // d_in[1] = eb_offset : mathematically unused
    const float* W0  = (const float*)d_in[2];
    const float* W1  = (const float*)d_in[3];
    const float* W2  = (const float*)d_in[4];
    int n_idx   = in_sizes[0];
    int num_emb = in_sizes[2] / 3;

    int n4 = n_idx >> 2;
    int hist_blocks = (n4 + 255) / 256;
    if (hist_blocks < 1) hist_blocks = 1;
    k_hist<<<hist_blocks, 256>>>(idx, n_idx);

    int sweep_threads = (num_emb + 3) / 4;
    int sweep_blocks = (sweep_threads + 255) / 256;
    if (sweep_blocks < 1) sweep_blocks = 1;
    k_sweep<<<sweep_blocks, 256>>>(W0, W1, W2, num_emb);

    k_final<<<1, 32>>>((float*)d_out);
}

// round 3
// speedup vs baseline: 1.2053x; 1.2053x over previous
#include <cuda_runtime.h>
#include <cuda_bf16.h>

// out[k][d] = mult_k * sum_i W_k[eb_input[i]][d]   (offsets are mathematically dead:
// every index position belongs to some bag, and all bags are summed at the end).
//
// Structure: histogram (LTS-atomic bound, DRAM idle) fused with a 72MB table
// prefetch into L2 (DRAM work), then an L2-resident weighted sweep.

#define MAX_EMB 2000000

// 8MB u32 count scratch. Zero at module load; sweep re-zeroes after reading,
// so every graph replay sees a clean state.
__device__ unsigned int g_count[MAX_EMB];
// 9 double accumulators padded to 512B stride (distinct L2 slices).
__device__ double g_acc[9 * 64];

// ---------------------------------------------------------------------------
// Kernel 1: histogram + L2 prefetch of the three tables.
// Each thread: 1x int4 (4 REDs, fire-and-forget) + grid-stride float4 streaming
// loads over all tables (kept alive by a fake asm use; fills L2 for the sweep).
// ---------------------------------------------------------------------------
__global__ void k_hist_prefetch(const int* __restrict__ idx, int n_idx,
                                const float4* __restrict__ V0,
                                const float4* __restrict__ V1,
                                const float4* __restrict__ V2,
                                int nf4) {
    int t = blockIdx.x * blockDim.x + threadIdx.x;
    int T = gridDim.x * blockDim.x;
    int n4 = n_idx >> 2;

    if (t < n4) {
        int4 a = __ldcs((const int4*)idx + t);   // evict-first: don't pollute L2
        atomicAdd(&g_count[a.x], 1u);
        atomicAdd(&g_count[a.y], 1u);
        atomicAdd(&g_count[a.z], 1u);
        atomicAdd(&g_count[a.w], 1u);
    }
    if (blockIdx.x == 0) {                       // scalar tail
        int rem = n_idx & 3;
        if ((int)threadIdx.x < rem)
            atomicAdd(&g_count[idx[(n4 << 2) + threadIdx.x]], 1u);
    }

    // Prefetch tables into L2 (default policy fills L2). REDs above are
    // no-return, so these loads overlap the atomic drain.
    float s = 0.0f;
    for (int i = t; i < nf4; i += T) {
        float4 a = __ldg(V0 + i);
        float4 b = __ldg(V1 + i);
        float4 c = __ldg(V2 + i);
        s += a.x + a.y + a.z + a.w;
        s += b.x + b.y + b.z + b.w;
        s += c.x + c.y + c.z + c.w;
    }
    asm volatile("" :: "f"(s));                  // keep loads alive, no store
}

// ---------------------------------------------------------------------------
// Kernel 2: weighted sweep (exact R1 form — measured 10.4us from DRAM, now L2).
// Each thread: 4 rows (3 float4 per table); reads counts as uint4, re-zeroes.
// ---------------------------------------------------------------------------
__global__ void k_sweep(const float* __restrict__ W0,
                        const float* __restrict__ W1,
                        const float* __restrict__ W2,
                        int num_emb) {
    int t = blockIdx.x * blockDim.x + threadIdx.x;
    int r0 = t * 4;

    float acc[9];
#pragma unroll
    for (int k = 0; k < 9; k++) acc[k] = 0.0f;

    if (r0 + 4 <= num_emb) {
        uint4 c4 = *(const uint4*)&g_count[r0];
        *(uint4*)&g_count[r0] = make_uint4(0u, 0u, 0u, 0u);   // re-init for replay
        float c0 = (float)c4.x, c1 = (float)c4.y, c2 = (float)c4.z, c3 = (float)c4.w;

        const float* Ws[3] = {W0, W1, W2};
#pragma unroll
        for (int k = 0; k < 3; k++) {
            const float4* Wv = (const float4*)Ws[k] + 3 * t;   // 12 floats = 4 rows
            float4 a = __ldg(Wv + 0);
            float4 b = __ldg(Wv + 1);
            float4 d = __ldg(Wv + 2);
            // rows: r0: a.x a.y a.z | r0+1: a.w b.x b.y | r0+2: b.z b.w d.x | r0+3: d.y d.z d.w
            acc[3 * k + 0] += c0 * a.x + c1 * a.w + c2 * b.z + c3 * d.y;
            acc[3 * k + 1] += c0 * a.y + c1 * b.x + c2 * b.w + c3 * d.z;
            acc[3 * k + 2] += c0 * a.z + c1 * b.y + c2 * d.x + c3 * d.w;
        }
    } else if (r0 < num_emb) {
        for (int r = r0; r < num_emb; r++) {
            float c = (float)g_count[r];
            g_count[r] = 0u;
            const float* Ws[3] = {W0, W1, W2};
#pragma unroll
            for (int k = 0; k < 3; k++) {
                acc[3 * k + 0] += c * Ws[k][3 * r + 0];
                acc[3 * k + 1] += c * Ws[k][3 * r + 1];
                acc[3 * k + 2] += c * Ws[k][3 * r + 2];
            }
        }
    }

    // warp reduction
    unsigned lane = threadIdx.x & 31u;
    unsigned warp = threadIdx.x >> 5;
#pragma unroll
    for (int k = 0; k < 9; k++) {
#pragma unroll
        for (int o = 16; o > 0; o >>= 1)
            acc[k] += __shfl_down_sync(0xffffffffu, acc[k], o);
    }

    __shared__ float s_red[8][9];
    if (lane == 0) {
#pragma unroll
        for (int k = 0; k < 9; k++) s_red[warp][k] = acc[k];
    }
    __syncthreads();

    if (threadIdx.x < 9) {
        double s = 0.0;
#pragma unroll
        for (int w = 0; w < 8; w++) s += (double)s_red[w][threadIdx.x];
        atomicAdd(&g_acc[threadIdx.x * 64], s);
    }
}

// ---------------------------------------------------------------------------
// Kernel 3: scale, write output, re-zero accumulators for next replay.
// ---------------------------------------------------------------------------
__global__ void k_final(float* __restrict__ out) {
    int i = threadIdx.x;
    if (i < 9) {
        const float mult[3] = {5.0f, 10.0f, 6.0f};
        double v = g_acc[i * 64];
        g_acc[i * 64] = 0.0;
        out[i] = (float)((double)mult[i / 3] * v);
    }
}

// ---------------------------------------------------------------------------
extern "C" void kernel_launch(void* const* d_in, const int* in_sizes, int n_in,
                              void* d_out, int out_size) {
    const int*   idx = (const int*)d_in[0];
    // d_in[1] = eb_offset : mathematically unused
    const float* W0  = (const float*)d_in[2];
    const float* W1  = (const float*)d_in[3];
    const float* W2  = (const float*)d_in[4];
    int n_idx   = in_sizes[0];
    int num_emb = in_sizes[2] / 3;
    int nf4     = (num_emb * 3) / 4;   // float4 count per table (6M/4 = 1.5M)

    int n4 = n_idx >> 2;
    int hist_blocks = (n4 + 255) / 256;
    if (hist_blocks < 1) hist_blocks = 1;
    k_hist_prefetch<<<hist_blocks, 256>>>(idx, n_idx,
                                          (const float4*)W0,
                                          (const float4*)W1,
                                          (const float4*)W2, nf4);

    int sweep_threads = (num_emb + 3) / 4;
    int sweep_blocks = (sweep_threads + 255) / 256;
    if (sweep_blocks < 1) sweep_blocks = 1;
    k_sweep<<<sweep_blocks, 256>>>(W0, W1, W2, num_emb);

    k_final<<<1, 32>>>((float*)d_out);
}